// round 13
// baseline (speedup 1.0000x reference)
#include <cuda_runtime.h>
#include <cuda_bf16.h>
#include <cstdint>
#include <cstddef>

// ---------------- problem constants ----------------
#define HW    16384            // 128*128
#define PTOT  131072           // 8*128*128 = 1<<17

// ---------------- scratch (device globals; no allocation) ----------------
__device__ __align__(16) __nv_bfloat16 g_qkv [(size_t)PTOT * 288];  // PLANAR [288][P]
__device__ __align__(16) __nv_bfloat16 g_attn[(size_t)PTOT * 96];   // row-major P x 96
__device__ __align__(16) __nv_bfloat16 g_wb  [110592];              // bf16 weights

// ---------------- helpers ----------------
__device__ __forceinline__ uint32_t smem_u32(const void* p) {
    uint32_t a;
    asm("{ .reg .u64 t; cvta.to.shared.u64 t, %1; cvt.u32.u64 %0, t; }"
        : "=r"(a) : "l"(p));
    return a;
}
__device__ __forceinline__ void cpa16(uint32_t dst, const void* src) {
    asm volatile("cp.async.cg.shared.global [%0], [%1], 16;"
                 :: "r"(dst), "l"(src));
}
__device__ __forceinline__ void cp_commit() {
    asm volatile("cp.async.commit_group;" ::: "memory");
}
__device__ __forceinline__ void cp_wait0() {
    asm volatile("cp.async.wait_group 0;" ::: "memory");
}
#define LDSM4(r0, r1, r2, r3, addr) \
    asm volatile("ldmatrix.sync.aligned.m8n8.x4.shared.b16 {%0,%1,%2,%3}, [%4];" \
                 : "=r"(r0), "=r"(r1), "=r"(r2), "=r"(r3) : "r"(addr))
#define LDSM2(r0, r1, addr) \
    asm volatile("ldmatrix.sync.aligned.m8n8.x2.shared.b16 {%0,%1}, [%2];" \
                 : "=r"(r0), "=r"(r1) : "r"(addr))
__device__ __forceinline__ void mma16(float* d, const uint32_t* a,
                                      const uint32_t* b) {
    asm volatile(
        "mma.sync.aligned.m16n8k16.row.col.f32.bf16.bf16.f32 "
        "{%0,%1,%2,%3}, {%4,%5,%6,%7}, {%8,%9}, {%0,%1,%2,%3};"
        : "+f"(d[0]), "+f"(d[1]), "+f"(d[2]), "+f"(d[3])
        : "r"(a[0]), "r"(a[1]), "r"(a[2]), "r"(a[3]), "r"(b[0]), "r"(b[1]));
}
__device__ __forceinline__ uint32_t packbf(float a, float b) {
    __nv_bfloat162 p = __floats2bfloat162_rn(a, b);
    return *(uint32_t*)&p;
}
__device__ __forceinline__ float bflo(uint32_t u) {
    return __uint_as_float(u << 16);
}
__device__ __forceinline__ float bfhi(uint32_t u) {
    return __uint_as_float(u & 0xffff0000u);
}
// tanh-form GELU via hardware MUFU.TANH.
__device__ __forceinline__ float gelu_f(float t) {
    float u = 0.7978845608f * t * fmaf(t * t, 0.044715f, 1.0f);
    float th;
    asm("tanh.approx.f32 %0, %1;" : "=f"(th) : "f"(u));
    return 0.5f * t * (1.f + th);
}

// B-fragment ldmatrix relative addresses, row stride SB bytes.
template <int SB>
__device__ __forceinline__ void bfrag_addrs(int wc, int lane,
                                            uint32_t& bA01, uint32_t& bA2) {
    int rw = lane & 7;
    int hi16 = (lane >> 3) & 1;                // byte +16 = k 8..15
    bA01 = (uint32_t)((wc * 24 + ((lane >> 4) << 3) + rw) * SB + (hi16 << 4));
    bA2  = (uint32_t)((wc * 24 + 16 + rw) * SB + (hi16 << 4));
}

// ---------------- weight conversion fp32 -> bf16 ----------------
__global__ __launch_bounds__(256)
void round_w(const float* __restrict__ qkv, const float* __restrict__ proj,
             const float* __restrict__ fc1, const float* __restrict__ fc2) {
    int i = blockIdx.x * 256 + threadIdx.x;
    float v;
    if (i < 27648)        v = qkv[i];
    else if (i < 36864)   v = proj[i - 27648];
    else if (i < 73728)   v = fc1[i - 36864];
    else                  v = fc2[i - 73728];
    g_wb[i] = __float2bfloat16_rn(v);
}

// ================= fused LN1 + qkv GEMM (256 thr, 2 CTAs/SM) =================
#define A_SZ 91904

__global__ __launch_bounds__(256, 2)
void k_ln1_qkv(const float* __restrict__ x, const __nv_bfloat16* __restrict__ wq,
               const float* __restrict__ lnw, const float* __restrict__ lnb,
               __nv_bfloat16* __restrict__ qkv) {
    extern __shared__ __align__(16) char dsm[];
    const uint32_t sb = smem_u32(dsm);
    float* sXp = (float*)dsm;                       // stride 132
    __nv_bfloat16* sDb = (__nv_bfloat16*)(dsm + 39936);
    uint32_t* sAw = (uint32_t*)(dsm + 65280);
    const uint32_t sAa = sb + 65280;

    const int tid = threadIdx.x;
    const int m0 = blockIdx.x * 128;
    const int bb = m0 >> 14, ss0 = m0 & 16383;

    // ---- stage x (planar) channel-major into sXp ----
#pragma unroll
    for (int it = 0; it < 12; it++) {               // 3072 x 16B
        int u = it * 256 + tid;
        int c = u >> 5, q = u & 31;
        cpa16(sb + (uint32_t)(c * 528 + q * 16),
              x + (((size_t)(bb * 96 + c)) << 14) + ss0 + q * 4);
    }
    cp_commit(); cp_wait0();
    __syncthreads();

    // ---- LN1: two threads per pixel ----
    {
        const int px = tid >> 1, half = tid & 1;
        float sum = 0.f, sq = 0.f;
#pragma unroll
        for (int i = 0; i < 48; i++) {
            float v = sXp[(half * 48 + i) * 132 + px];
            sum += v;
            sq = fmaf(v, v, sq);
        }
        sum += __shfl_xor_sync(0xffffffffu, sum, 1);
        sq  += __shfl_xor_sync(0xffffffffu, sq, 1);
        float mu = sum * (1.f / 96.f);
        float rs = rsqrtf(sq * (1.f / 96.f) - mu * mu + 1e-5f);
#pragma unroll
        for (int i = 0; i < 24; i++) {
            int c = half * 48 + 2 * i;
            float a0 = (sXp[c * 132 + px] - mu) * rs * __ldg(lnw + c)
                     + __ldg(lnb + c);
            float a1 = (sXp[(c + 1) * 132 + px] - mu) * rs * __ldg(lnw + c + 1)
                     + __ldg(lnb + c + 1);
            sAw[px * 52 + half * 24 + i] = packbf(a0, a1);
        }
    }
    __syncthreads();                                // sXp dead; sW region live

    // ---- GEMM over 3 N-blocks, double-buffered weights ----
    const int lane = tid & 31;
    const int wid = tid >> 5;
    const int wr = wid >> 2, wc = wid & 3;
    const int g = lane >> 2, tig = lane & 3;

    uint32_t aAddr[4];
#pragma unroll
    for (int i = 0; i < 4; i++)
        aAddr[i] = sAa + (uint32_t)((wr * 64 + i * 16 + (lane & 15)) * 208
                                    + (lane >> 4) * 16);
    uint32_t bA01, bA2;
    bfrag_addrs<208>(wc, lane, bA01, bA2);

    // preload nb0 weights into buf0
    for (int u = tid; u < 1152; u += 256) {
        int rr = u / 12, cc = u - rr * 12;
        cpa16(sb + (uint32_t)(rr * 208 + cc * 16), wq + rr * 96 + cc * 8);
    }
    cp_commit();

#pragma unroll 1
    for (int nb = 0; nb < 3; nb++) {
        cp_wait0();
        __syncthreads();
        if (nb < 2) {                                // prefetch nb+1
            const __nv_bfloat16* Wn = wq + (size_t)(nb + 1) * 9216;
            uint32_t dst = sb + (uint32_t)(((nb + 1) & 1) * 19968);
            for (int u = tid; u < 1152; u += 256) {
                int rr = u / 12, cc = u - rr * 12;
                cpa16(dst + (uint32_t)(rr * 208 + cc * 16), Wn + rr * 96 + cc * 8);
            }
            cp_commit();
        }
        const uint32_t wb = sb + (uint32_t)((nb & 1) * 19968);

        float acc[4][3][4];
#pragma unroll
        for (int i = 0; i < 4; i++)
#pragma unroll
            for (int j = 0; j < 3; j++)
#pragma unroll
                for (int q = 0; q < 4; q++) acc[i][j][q] = 0.f;

#pragma unroll
        for (int ks = 0; ks < 6; ks++) {
            uint32_t a[4][4], b01[4], b2x[2];
            LDSM4(b01[0], b01[1], b01[2], b01[3], wb + bA01 + (uint32_t)(ks * 32));
            LDSM2(b2x[0], b2x[1], wb + bA2 + (uint32_t)(ks * 32));
#pragma unroll
            for (int i = 0; i < 4; i++)
                LDSM4(a[i][0], a[i][1], a[i][2], a[i][3],
                      aAddr[i] + (uint32_t)(ks * 32));
#pragma unroll
            for (int i = 0; i < 4; i++) {
                mma16(acc[i][0], a[i], b01);
                mma16(acc[i][1], a[i], b01 + 2);
                mma16(acc[i][2], a[i], b2x);
            }
        }

        // stage D bf16 [col][132]
#pragma unroll
        for (int i = 0; i < 4; i++)
#pragma unroll
            for (int j = 0; j < 3; j++) {
                int row = wr * 64 + i * 16 + g;
                int col = wc * 24 + j * 8 + 2 * tig;
                sDb[col * 132 + row]           = __float2bfloat16_rn(acc[i][j][0]);
                sDb[(col + 1) * 132 + row]     = __float2bfloat16_rn(acc[i][j][1]);
                sDb[col * 132 + row + 8]       = __float2bfloat16_rn(acc[i][j][2]);
                sDb[(col + 1) * 132 + row + 8] = __float2bfloat16_rn(acc[i][j][3]);
            }
        __syncthreads();
        const uint32_t* sDu = (const uint32_t*)sDb;
#pragma unroll
        for (int u = tid; u < 6144; u += 256) {
            int col = u >> 6, q = u & 63;
            ((uint32_t*)(qkv + (((size_t)(nb * 96 + col)) << 17) + m0))[q]
                = sDu[col * 66 + q];
        }
        __syncthreads();
    }
}

// ================= dilated attention: 4 rows/CTA, 2 px/thread ===============
// SMEM u32: k [cp:8][row:10][144] @0 (11520), v same @11520. 92160 B.
// pads (u32 0..7, 136..143 per row) zeroed; OOB rows zeroed inline.
#define ATT_SZ 92160

__global__ __launch_bounds__(256)
void attn_kernel(const __nv_bfloat16* __restrict__ qkvp,
                 __nv_bfloat16* __restrict__ attn) {
    extern __shared__ __align__(16) uint32_t sm32[];
    const int tid = threadIdx.x;
    const int b = blockIdx.x >> 5;
    const int h0 = (blockIdx.x & 31) << 2;           // 4 rows per CTA
    const int hd = blockIdx.y;
    const int grp = hd >> 1;
    const int dil = grp + 1;
    const int cb = grp * 32 + (hd & 1) * 16;
    const int nr = 4 + 2 * dil;                      // 6 / 8 / 10 rows

    // zero w-pads: 8cp x 10rows x 4 uint4 x 2 tensors = 640 uint4
    {
        uint4 z = make_uint4(0u, 0u, 0u, 0u);
        for (int u = tid; u < 640; u += 256) {
            int t = u / 320, rem = u - t * 320;
            int q4 = rem >> 2;                       // cp*10+row
            int cp = q4 / 10, row = q4 - cp * 10;
            int f = rem & 3;
            int off = t * 11520 + cp * 1440 + row * 144
                    + (f < 2 ? f * 4 : 128 + f * 4);
            *(uint4*)(sm32 + off) = z;
        }
    }

    // stage k/v rows; OOB rows zeroed inline
    const int baseh = h0 - dil;
    for (int u = tid; u < (nr << 7); u += 256) {
        int q8 = u & 15, seg = u >> 4;
        int cp = seg / nr, row = seg - cp * nr;
        int hr = baseh + row;
        int di = cp * 1440 + row * 144 + 8 + q8 * 8;
        if ((unsigned)hr < 128u) {
            size_t gofs = ((size_t)b << 14) + (hr << 7) + q8 * 8;
            uint4 k0 = *(const uint4*)(qkvp + (((size_t)(96 + cb + 2 * cp)) << 17) + gofs);
            uint4 k1 = *(const uint4*)(qkvp + (((size_t)(97 + cb + 2 * cp)) << 17) + gofs);
            uint4 v0 = *(const uint4*)(qkvp + (((size_t)(192 + cb + 2 * cp)) << 17) + gofs);
            uint4 v1 = *(const uint4*)(qkvp + (((size_t)(193 + cb + 2 * cp)) << 17) + gofs);
            uint4 o;
            o.x = __byte_perm(k0.x, k1.x, 0x5410); o.y = __byte_perm(k0.x, k1.x, 0x7632);
            o.z = __byte_perm(k0.y, k1.y, 0x5410); o.w = __byte_perm(k0.y, k1.y, 0x7632);
            *(uint4*)(sm32 + di) = o;
            o.x = __byte_perm(k0.z, k1.z, 0x5410); o.y = __byte_perm(k0.z, k1.z, 0x7632);
            o.z = __byte_perm(k0.w, k1.w, 0x5410); o.w = __byte_perm(k0.w, k1.w, 0x7632);
            *(uint4*)(sm32 + di + 4) = o;
            o.x = __byte_perm(v0.x, v1.x, 0x5410); o.y = __byte_perm(v0.x, v1.x, 0x7632);
            o.z = __byte_perm(v0.y, v1.y, 0x5410); o.w = __byte_perm(v0.y, v1.y, 0x7632);
            *(uint4*)(sm32 + di + 11520) = o;
            o.x = __byte_perm(v0.z, v1.z, 0x5410); o.y = __byte_perm(v0.z, v1.z, 0x7632);
            o.z = __byte_perm(v0.w, v1.w, 0x5410); o.w = __byte_perm(v0.w, v1.w, 0x7632);
            *(uint4*)(sm32 + di + 11524) = o;
        } else {
            uint4 z = make_uint4(0u, 0u, 0u, 0u);
            *(uint4*)(sm32 + di) = z;         *(uint4*)(sm32 + di + 4) = z;
            *(uint4*)(sm32 + di + 11520) = z; *(uint4*)(sm32 + di + 11524) = z;
        }
    }
    __syncthreads();

    // 2 pixels per thread: px = tid + pp*256
    float oL[2][8], oH[2][8];
#pragma unroll 1
    for (int pp = 0; pp < 2; pp++) {
        const int px = tid + pp * 256;
        const int r = px >> 7, w = px & 127;
        const size_t p = ((size_t)b << 14) + ((size_t)(h0 + r) << 7) + w;

        float ql[8], qh[8];
#pragma unroll
        for (int cp = 0; cp < 8; cp++) {
            ql[cp] = __bfloat162float(qkvp[(((size_t)(cb + 2 * cp)) << 17) + p]);
            qh[cp] = __bfloat162float(qkvp[(((size_t)(cb + 2 * cp + 1)) << 17) + p]);
        }

        float sc[9];
#pragma unroll
        for (int i = 0; i < 3; i++)
#pragma unroll
            for (int j = 0; j < 3; j++) {
                int base = (r + i * dil) * 144 + (8 + w + (j - 1) * dil);
                float d = 0.f;
#pragma unroll
                for (int cp = 0; cp < 8; cp++) {
                    uint32_t u = sm32[cp * 1440 + base];
                    d = fmaf(ql[cp], bflo(u), d);
                    d = fmaf(qh[cp], bfhi(u), d);
                }
                sc[i * 3 + j] = d * 0.25f;
            }

        float mx = sc[0];
#pragma unroll
        for (int k = 1; k < 9; k++) mx = fmaxf(mx, sc[k]);
        float ssum = 0.f;
#pragma unroll
        for (int k = 0; k < 9; k++) { sc[k] = __expf(sc[k] - mx); ssum += sc[k]; }
        float inv = 1.f / ssum;

#pragma unroll
        for (int cp = 0; cp < 8; cp++) { oL[pp][cp] = 0.f; oH[pp][cp] = 0.f; }
#pragma unroll
        for (int i = 0; i < 3; i++)
#pragma unroll
            for (int j = 0; j < 3; j++) {
                float wgt = sc[i * 3 + j] * inv;
                int base = 11520 + (r + i * dil) * 144 + (8 + w + (j - 1) * dil);
#pragma unroll
                for (int cp = 0; cp < 8; cp++) {
                    uint32_t u = sm32[cp * 1440 + base];
                    oL[pp][cp] = fmaf(wgt, bflo(u), oL[pp][cp]);
                    oH[pp][cp] = fmaf(wgt, bfhi(u), oH[pp][cp]);
                }
            }
    }

    // restage (k/v reads done) -> coalesced bf16 stores
    __syncthreads();
#pragma unroll
    for (int pp = 0; pp < 2; pp++)
#pragma unroll
        for (int cp = 0; cp < 8; cp++)
            sm32[(tid + pp * 256) * 17 + cp] = packbf(oL[pp][cp], oH[pp][cp]);
    __syncthreads();
    const size_t p0 = ((size_t)b << 14) + ((size_t)h0 << 7);
#pragma unroll
    for (int u = tid; u < 4096; u += 256) {
        int px = u >> 3, wq = u & 7;
        ((uint32_t*)(attn + (p0 + px) * 96 + cb))[wq] = sm32[px * 17 + wq];
    }
}

// ================= mega-fused proj+res+LN2+MLP (unchanged from R12) =========
#define M_SZ 91392

__global__ __launch_bounds__(256, 2)
void k_pm(const __nv_bfloat16* __restrict__ attn,
          const __nv_bfloat16* __restrict__ wp, const float* __restrict__ pb,
          const float* __restrict__ x,
          const __nv_bfloat16* __restrict__ w1, const float* __restrict__ b1,
          const __nv_bfloat16* __restrict__ w2, const float* __restrict__ b2,
          const float* __restrict__ lnw, const float* __restrict__ lnb,
          float* __restrict__ out) {
    extern __shared__ __align__(16) char dsm[];
    const uint32_t sb = smem_u32(dsm);
    float* sX = (float*)dsm;
    uint32_t* sAw = (uint32_t*)(dsm + 24832);
    uint32_t* sHsU = (uint32_t*)(dsm + 38144);
    float* sEp = (float*)(dsm + 51456);
    const uint32_t sAa = sb + 24832;
    const uint32_t sHa = sb + 38144;
    const uint32_t W0 = sb + 51456;
    const uint32_t W1 = sb + 71424;

    const int tid = threadIdx.x;
    const int lane = tid & 31;
    const int wid = tid >> 5;
    const int wr = wid >> 2, wc = wid & 3;
    const int g = lane >> 2, tig = lane & 3;
    const int m0 = blockIdx.x * 64;
    const int bb = m0 >> 14, ss0 = m0 & 16383;

    uint32_t aAddr[2], hAddr[2];
#pragma unroll
    for (int i = 0; i < 2; i++) {
        int row = wr * 32 + i * 16 + (lane & 15);
        aAddr[i] = sAa + (uint32_t)(row * 208 + (lane >> 4) * 16);
        hAddr[i] = sHa + (uint32_t)(row * 208 + (lane >> 4) * 16);
    }
    uint32_t bA01, bA2;
    bfrag_addrs<208>(wc, lane, bA01, bA2);

    auto issue_chunk = [&](const __nv_bfloat16* W, int ld, int col0,
                           uint32_t buf) {
        for (int u = tid; u < 1152; u += 256) {
            int rr = u / 12, cc = u - rr * 12;
            cpa16(buf + (uint32_t)(rr * 208 + cc * 16),
                  W + (size_t)rr * ld + col0 + cc * 8);
        }
        cp_commit();
    };

    const __nv_bfloat16* Ab = attn + (size_t)m0 * 96;
#pragma unroll
    for (int it = 0; it < 3; it++) {
        int u = it * 256 + tid;
        int rr = u / 12, cc = u - rr * 12;
        cpa16(sAa + (uint32_t)(rr * 208 + cc * 16), Ab + (size_t)rr * 96 + cc * 8);
    }
    issue_chunk(wp, 96, 0, W0);

#define CHUNK_MMA(ACC, A0, A1, WBUF)                                          \
    do {                                                                      \
        _Pragma("unroll")                                                     \
        for (int ks = 0; ks < 6; ks++) {                                      \
            uint32_t a[2][4], b01[4], b2x[2];                                 \
            LDSM4(b01[0], b01[1], b01[2], b01[3],                             \
                  (WBUF) + bA01 + (uint32_t)(ks * 32));                       \
            LDSM2(b2x[0], b2x[1], (WBUF) + bA2 + (uint32_t)(ks * 32));        \
            LDSM4(a[0][0], a[0][1], a[0][2], a[0][3],                         \
                  (A0) + (uint32_t)(ks * 32));                                \
            LDSM4(a[1][0], a[1][1], a[1][2], a[1][3],                         \
                  (A1) + (uint32_t)(ks * 32));                                \
            _Pragma("unroll")                                                 \
            for (int i = 0; i < 2; i++) {                                     \
                mma16((ACC)[i][0], a[i], b01);                                \
                mma16((ACC)[i][1], a[i], b01 + 2);                            \
                mma16((ACC)[i][2], a[i], b2x);                                \
            }                                                                 \
        }                                                                     \
    } while (0)

    float acc[2][3][4];
#pragma unroll
    for (int i = 0; i < 2; i++)
#pragma unroll
        for (int j = 0; j < 3; j++)
#pragma unroll
            for (int q = 0; q < 4; q++) acc[i][j][q] = 0.f;

    cp_wait0(); __syncthreads();
    issue_chunk(w1, 96, 0, W1);
    CHUNK_MMA(acc, aAddr[0], aAddr[1], W0);

#pragma unroll
    for (int i = 0; i < 2; i++)
#pragma unroll
        for (int j = 0; j < 3; j++) {
            int row = wr * 32 + i * 16 + g;
            int col = wc * 24 + j * 8 + 2 * tig;
            float bi0 = __ldg(pb + col), bi1 = __ldg(pb + col + 1);
            sX[row * 97 + col]           = acc[i][j][0] + bi0;
            sX[row * 97 + col + 1]       = acc[i][j][1] + bi1;
            sX[(row + 8) * 97 + col]     = acc[i][j][2] + bi0;
            sX[(row + 8) * 97 + col + 1] = acc[i][j][3] + bi1;
        }
    __syncthreads();

#pragma unroll
    for (int u = tid; u < 6144; u += 256) {
        int col = u >> 6, px = u & 63;
        sX[px * 97 + col] += __ldg(x + (((size_t)(bb * 96 + col)) << 14) + ss0 + px);
    }
    __syncthreads();

    {
        const int px = tid >> 2, q = tid & 3;
        const float* xr = sX + px * 97 + q * 24;
        float sum = 0.f, sq = 0.f;
#pragma unroll
        for (int i = 0; i < 24; i++) {
            float v = xr[i];
            sum += v;
            sq = fmaf(v, v, sq);
        }
        sum += __shfl_xor_sync(0xffffffffu, sum, 1);
        sq  += __shfl_xor_sync(0xffffffffu, sq, 1);
        sum += __shfl_xor_sync(0xffffffffu, sum, 2);
        sq  += __shfl_xor_sync(0xffffffffu, sq, 2);
        float mu = sum * (1.f / 96.f);
        float rs = rsqrtf(sq * (1.f / 96.f) - mu * mu + 1e-5f);
#pragma unroll
        for (int i = 0; i < 12; i++) {
            int c = q * 24 + 2 * i;
            float a0 = (xr[2 * i] - mu) * rs * __ldg(lnw + c) + __ldg(lnb + c);
            float a1 = (xr[2 * i + 1] - mu) * rs * __ldg(lnw + c + 1)
                     + __ldg(lnb + c + 1);
            sAw[px * 52 + q * 12 + i] = packbf(a0, a1);
        }
    }

    float acc2[2][3][4];
#pragma unroll
    for (int i = 0; i < 2; i++)
#pragma unroll
        for (int j = 0; j < 3; j++)
#pragma unroll
            for (int q = 0; q < 4; q++) acc2[i][j][q] = 0.f;

    uint32_t aF[3][2][4];

#pragma unroll 1
    for (int nb = 0; nb < 4; nb++) {
        cp_wait0(); __syncthreads();
        issue_chunk(w2, 384, nb * 96, W0);
        if (nb == 0) {
#pragma unroll
            for (int ks = 0; ks < 3; ks++) {
                LDSM4(aF[ks][0][0], aF[ks][0][1], aF[ks][0][2], aF[ks][0][3],
                      aAddr[0] + (uint32_t)(ks * 32));
                LDSM4(aF[ks][1][0], aF[ks][1][1], aF[ks][1][2], aF[ks][1][3],
                      aAddr[1] + (uint32_t)(ks * 32));
            }
        }
        float a1c[2][3][4];
#pragma unroll
        for (int i = 0; i < 2; i++)
#pragma unroll
            for (int j = 0; j < 3; j++)
#pragma unroll
                for (int q = 0; q < 4; q++) a1c[i][j][q] = 0.f;
#pragma unroll
        for (int ks = 0; ks < 3; ks++) {
            uint32_t b01[4], b2x[2];
            LDSM4(b01[0], b01[1], b01[2], b01[3],
                  W1 + bA01 + (uint32_t)(ks * 32));
            LDSM2(b2x[0], b2x[1], W1 + bA2 + (uint32_t)(ks * 32));
#pragma unroll
            for (int i = 0; i < 2; i++) {
                mma16(a1c[i][0], aF[ks][i], b01);
                mma16(a1c[i][1], aF[ks][i], b01 + 2);
                mma16(a1c[i][2], aF[ks][i], b2x);
            }
        }
#pragma unroll
        for (int ks = 3; ks < 6; ks++) {
            uint32_t a[2][4], b01[4], b2x[2];
            LDSM4(b01[0], b01[1], b01[2], b01[3],
                  W1 + bA01 + (uint32_t)(ks * 32));
            LDSM2(b2x[0], b2x[1], W1 + bA2 + (uint32_t)(ks * 32));
            LDSM4(a[0][0], a[0][1], a[0][2], a[0][3],
                  aAddr[0] + (uint32_t)(ks * 32));
            LDSM4(a[1][0], a[1][1], a[1][2], a[1][3],
                  aAddr[1] + (uint32_t)(ks * 32));
#pragma unroll
            for (int i = 0; i < 2; i++) {
                mma16(a1c[i][0], a[i], b01);
                mma16(a1c[i][1], a[i], b01 + 2);
                mma16(a1c[i][2], a[i], b2x);
            }
        }

#pragma unroll
        for (int i = 0; i < 2; i++)
#pragma unroll
            for (int j = 0; j < 3; j++) {
                int row = wr * 32 + i * 16 + g;
                int col = wc * 24 + j * 8 + 2 * tig;
                float bi0 = __ldg(b1 + nb * 96 + col);
                float bi1 = __ldg(b1 + nb * 96 + col + 1);
                float t0 = gelu_f(a1c[i][j][0] + bi0);
                float t1 = gelu_f(a1c[i][j][1] + bi1);
                float t2 = gelu_f(a1c[i][j][2] + bi0);
                float t3 = gelu_f(a1c[i][j][3] + bi1);
                sHsU[(row * 104 + col) >> 1]       = packbf(t0, t1);
                sHsU[((row + 8) * 104 + col) >> 1] = packbf(t2, t3);
            }

        cp_wait0(); __syncthreads();
        if (nb < 3)
            issue_chunk(w1 + (size_t)(nb + 1) * 9216, 96, 0, W1);
        CHUNK_MMA(acc2, hAddr[0], hAddr[1], W0);
    }
    __syncthreads();

#pragma unroll
    for (int i = 0; i < 2; i++)
#pragma unroll
        for (int j = 0; j < 3; j++) {
            int row = wr * 32 + i * 16 + g;
            int col = wc * 24 + j * 8 + 2 * tig;
            sEp[row * 97 + col]           = acc2[i][j][0];
            sEp[row * 97 + col + 1]       = acc2[i][j][1];
            sEp[(row + 8) * 97 + col]     = acc2[i][j][2];
            sEp[(row + 8) * 97 + col + 1] = acc2[i][j][3];
        }
    __syncthreads();
#pragma unroll
    for (int u = tid; u < 6144; u += 256) {
        int col = u >> 6, px = u & 63;
        float val = sEp[px * 97 + col] + __ldg(b2 + col) + sX[px * 97 + col];
        out[(((size_t)(bb * 96 + col)) << 14) + ss0 + px] = val;
    }
#undef CHUNK_MMA
}

// ---------------- launch ----------------
extern "C" void kernel_launch(void* const* d_in, const int* in_sizes, int n_in,
                              void* d_out, int out_size) {
    (void)in_sizes; (void)n_in; (void)out_size;
    const float* x      = (const float*)d_in[0];
    const float* qkv_w  = (const float*)d_in[1];
    const float* proj_w = (const float*)d_in[2];
    const float* proj_b = (const float*)d_in[3];
    const float* ln1w   = (const float*)d_in[4];
    const float* ln1b   = (const float*)d_in[5];
    const float* ln2w   = (const float*)d_in[6];
    const float* ln2b   = (const float*)d_in[7];
    const float* fc1w   = (const float*)d_in[8];
    const float* fc1b   = (const float*)d_in[9];
    const float* fc2w   = (const float*)d_in[10];
    const float* fc2b   = (const float*)d_in[11];
    float* out = (float*)d_out;

    cudaFuncSetAttribute(k_ln1_qkv,
                         cudaFuncAttributeMaxDynamicSharedMemorySize, A_SZ);
    cudaFuncSetAttribute(attn_kernel,
                         cudaFuncAttributeMaxDynamicSharedMemorySize, ATT_SZ);
    cudaFuncSetAttribute(k_pm,
                         cudaFuncAttributeMaxDynamicSharedMemorySize, M_SZ);

    __nv_bfloat16 *pqkv, *pattn, *pwb;
    cudaGetSymbolAddress((void**)&pqkv, g_qkv);
    cudaGetSymbolAddress((void**)&pattn, g_attn);
    cudaGetSymbolAddress((void**)&pwb, g_wb);

    round_w<<<432, 256>>>(qkv_w, proj_w, fc1w, fc2w);
    k_ln1_qkv<<<PTOT / 128, 256, A_SZ>>>(x, pwb, ln1w, ln1b, pqkv);
    attn_kernel<<<dim3(256, 6), 256, ATT_SZ>>>(pqkv, pattn);
    k_pm<<<PTOT / 64, 256, M_SZ>>>(pattn, pwb + 27648, proj_b, x,
                                   pwb + 36864, fc1b, pwb + 73728, fc2b,
                                   ln2w, ln2b, out);
}

// round 14
// speedup vs baseline: 1.0193x; 1.0193x over previous
#include <cuda_runtime.h>
#include <cuda_bf16.h>
#include <cstdint>
#include <cstddef>

// ---------------- problem constants ----------------
#define HW    16384            // 128*128
#define PTOT  131072           // 8*128*128 = 1<<17

// ---------------- scratch (device globals; no allocation) ----------------
__device__ __align__(16) __nv_bfloat16 g_qkv [(size_t)PTOT * 288];  // PLANAR [288][P]
__device__ __align__(16) __nv_bfloat16 g_attn[(size_t)PTOT * 96];   // row-major P x 96
__device__ __align__(16) __nv_bfloat16 g_wb  [110592];              // bf16 weights

// ---------------- helpers ----------------
__device__ __forceinline__ uint32_t smem_u32(const void* p) {
    uint32_t a;
    asm("{ .reg .u64 t; cvta.to.shared.u64 t, %1; cvt.u32.u64 %0, t; }"
        : "=r"(a) : "l"(p));
    return a;
}
__device__ __forceinline__ void cpa16(uint32_t dst, const void* src) {
    asm volatile("cp.async.cg.shared.global [%0], [%1], 16;"
                 :: "r"(dst), "l"(src));
}
__device__ __forceinline__ void cp_commit() {
    asm volatile("cp.async.commit_group;" ::: "memory");
}
__device__ __forceinline__ void cp_wait0() {
    asm volatile("cp.async.wait_group 0;" ::: "memory");
}
#define LDSM4(r0, r1, r2, r3, addr) \
    asm volatile("ldmatrix.sync.aligned.m8n8.x4.shared.b16 {%0,%1,%2,%3}, [%4];" \
                 : "=r"(r0), "=r"(r1), "=r"(r2), "=r"(r3) : "r"(addr))
#define LDSM2(r0, r1, addr) \
    asm volatile("ldmatrix.sync.aligned.m8n8.x2.shared.b16 {%0,%1}, [%2];" \
                 : "=r"(r0), "=r"(r1) : "r"(addr))
__device__ __forceinline__ void mma16(float* d, const uint32_t* a,
                                      const uint32_t* b) {
    asm volatile(
        "mma.sync.aligned.m16n8k16.row.col.f32.bf16.bf16.f32 "
        "{%0,%1,%2,%3}, {%4,%5,%6,%7}, {%8,%9}, {%0,%1,%2,%3};"
        : "+f"(d[0]), "+f"(d[1]), "+f"(d[2]), "+f"(d[3])
        : "r"(a[0]), "r"(a[1]), "r"(a[2]), "r"(a[3]), "r"(b[0]), "r"(b[1]));
}
__device__ __forceinline__ uint32_t packbf(float a, float b) {
    __nv_bfloat162 p = __floats2bfloat162_rn(a, b);
    return *(uint32_t*)&p;
}
__device__ __forceinline__ float bflo(uint32_t u) {
    return __uint_as_float(u << 16);
}
__device__ __forceinline__ float bfhi(uint32_t u) {
    return __uint_as_float(u & 0xffff0000u);
}
// tanh-form GELU via hardware MUFU.TANH.
__device__ __forceinline__ float gelu_f(float t) {
    float u = 0.7978845608f * t * fmaf(t * t, 0.044715f, 1.0f);
    float th;
    asm("tanh.approx.f32 %0, %1;" : "=f"(th) : "f"(u));
    return 0.5f * t * (1.f + th);
}

// B-fragment ldmatrix relative addresses, row stride SB bytes.
template <int SB>
__device__ __forceinline__ void bfrag_addrs(int wc, int lane,
                                            uint32_t& bA01, uint32_t& bA2) {
    int rw = lane & 7;
    int hi16 = (lane >> 3) & 1;                // byte +16 = k 8..15
    bA01 = (uint32_t)((wc * 24 + ((lane >> 4) << 3) + rw) * SB + (hi16 << 4));
    bA2  = (uint32_t)((wc * 24 + 16 + rw) * SB + (hi16 << 4));
}

// ---------------- weight conversion fp32 -> bf16 ----------------
__global__ __launch_bounds__(256)
void round_w(const float* __restrict__ qkv, const float* __restrict__ proj,
             const float* __restrict__ fc1, const float* __restrict__ fc2) {
    int i = blockIdx.x * 256 + threadIdx.x;
    float v;
    if (i < 27648)        v = qkv[i];
    else if (i < 36864)   v = proj[i - 27648];
    else if (i < 73728)   v = fc1[i - 36864];
    else                  v = fc2[i - 73728];
    g_wb[i] = __float2bfloat16_rn(v);
}

// ================= fused LN1 + qkv GEMM (256 thr, 2 CTAs/SM) =================
#define A_SZ 91904

__global__ __launch_bounds__(256, 2)
void k_ln1_qkv(const float* __restrict__ x, const __nv_bfloat16* __restrict__ wq,
               const float* __restrict__ lnw, const float* __restrict__ lnb,
               __nv_bfloat16* __restrict__ qkv) {
    extern __shared__ __align__(16) char dsm[];
    const uint32_t sb = smem_u32(dsm);
    float* sXp = (float*)dsm;                       // stride 132
    __nv_bfloat16* sDb = (__nv_bfloat16*)(dsm + 39936);
    uint32_t* sAw = (uint32_t*)(dsm + 65280);
    const uint32_t sAa = sb + 65280;

    const int tid = threadIdx.x;
    const int m0 = blockIdx.x * 128;
    const int bb = m0 >> 14, ss0 = m0 & 16383;

    // ---- stage x (planar) channel-major into sXp ----
#pragma unroll
    for (int it = 0; it < 12; it++) {               // 3072 x 16B
        int u = it * 256 + tid;
        int c = u >> 5, q = u & 31;
        cpa16(sb + (uint32_t)(c * 528 + q * 16),
              x + (((size_t)(bb * 96 + c)) << 14) + ss0 + q * 4);
    }
    cp_commit(); cp_wait0();
    __syncthreads();

    // ---- LN1: two threads per pixel ----
    {
        const int px = tid >> 1, half = tid & 1;
        float sum = 0.f, sq = 0.f;
#pragma unroll
        for (int i = 0; i < 48; i++) {
            float v = sXp[(half * 48 + i) * 132 + px];
            sum += v;
            sq = fmaf(v, v, sq);
        }
        sum += __shfl_xor_sync(0xffffffffu, sum, 1);
        sq  += __shfl_xor_sync(0xffffffffu, sq, 1);
        float mu = sum * (1.f / 96.f);
        float rs = rsqrtf(sq * (1.f / 96.f) - mu * mu + 1e-5f);
#pragma unroll
        for (int i = 0; i < 24; i++) {
            int c = half * 48 + 2 * i;
            float a0 = (sXp[c * 132 + px] - mu) * rs * __ldg(lnw + c)
                     + __ldg(lnb + c);
            float a1 = (sXp[(c + 1) * 132 + px] - mu) * rs * __ldg(lnw + c + 1)
                     + __ldg(lnb + c + 1);
            sAw[px * 52 + half * 24 + i] = packbf(a0, a1);
        }
    }
    __syncthreads();                                // sXp dead; sW region live

    // ---- GEMM over 3 N-blocks, double-buffered weights ----
    const int lane = tid & 31;
    const int wid = tid >> 5;
    const int wr = wid >> 2, wc = wid & 3;
    const int g = lane >> 2, tig = lane & 3;

    uint32_t aAddr[4];
#pragma unroll
    for (int i = 0; i < 4; i++)
        aAddr[i] = sAa + (uint32_t)((wr * 64 + i * 16 + (lane & 15)) * 208
                                    + (lane >> 4) * 16);
    uint32_t bA01, bA2;
    bfrag_addrs<208>(wc, lane, bA01, bA2);

    // preload nb0 weights into buf0
    for (int u = tid; u < 1152; u += 256) {
        int rr = u / 12, cc = u - rr * 12;
        cpa16(sb + (uint32_t)(rr * 208 + cc * 16), wq + rr * 96 + cc * 8);
    }
    cp_commit();

#pragma unroll 1
    for (int nb = 0; nb < 3; nb++) {
        cp_wait0();
        __syncthreads();
        if (nb < 2) {                                // prefetch nb+1
            const __nv_bfloat16* Wn = wq + (size_t)(nb + 1) * 9216;
            uint32_t dst = sb + (uint32_t)(((nb + 1) & 1) * 19968);
            for (int u = tid; u < 1152; u += 256) {
                int rr = u / 12, cc = u - rr * 12;
                cpa16(dst + (uint32_t)(rr * 208 + cc * 16), Wn + rr * 96 + cc * 8);
            }
            cp_commit();
        }
        const uint32_t wb = sb + (uint32_t)((nb & 1) * 19968);

        float acc[4][3][4];
#pragma unroll
        for (int i = 0; i < 4; i++)
#pragma unroll
            for (int j = 0; j < 3; j++)
#pragma unroll
                for (int q = 0; q < 4; q++) acc[i][j][q] = 0.f;

#pragma unroll
        for (int ks = 0; ks < 6; ks++) {
            uint32_t a[4][4], b01[4], b2x[2];
            LDSM4(b01[0], b01[1], b01[2], b01[3], wb + bA01 + (uint32_t)(ks * 32));
            LDSM2(b2x[0], b2x[1], wb + bA2 + (uint32_t)(ks * 32));
#pragma unroll
            for (int i = 0; i < 4; i++)
                LDSM4(a[i][0], a[i][1], a[i][2], a[i][3],
                      aAddr[i] + (uint32_t)(ks * 32));
#pragma unroll
            for (int i = 0; i < 4; i++) {
                mma16(acc[i][0], a[i], b01);
                mma16(acc[i][1], a[i], b01 + 2);
                mma16(acc[i][2], a[i], b2x);
            }
        }

        // stage D bf16 [col][132]
#pragma unroll
        for (int i = 0; i < 4; i++)
#pragma unroll
            for (int j = 0; j < 3; j++) {
                int row = wr * 64 + i * 16 + g;
                int col = wc * 24 + j * 8 + 2 * tig;
                sDb[col * 132 + row]           = __float2bfloat16_rn(acc[i][j][0]);
                sDb[(col + 1) * 132 + row]     = __float2bfloat16_rn(acc[i][j][1]);
                sDb[col * 132 + row + 8]       = __float2bfloat16_rn(acc[i][j][2]);
                sDb[(col + 1) * 132 + row + 8] = __float2bfloat16_rn(acc[i][j][3]);
            }
        __syncthreads();
        const uint32_t* sDu = (const uint32_t*)sDb;
#pragma unroll
        for (int u = tid; u < 6144; u += 256) {
            int col = u >> 6, q = u & 63;
            ((uint32_t*)(qkv + (((size_t)(nb * 96 + col)) << 17) + m0))[q]
                = sDu[col * 66 + q];
        }
        __syncthreads();
    }
}

// ================= dilated attention (R12 version: 2 rows/CTA) =============
__global__ __launch_bounds__(256)
void attn_kernel(const __nv_bfloat16* __restrict__ qkvp,
                 __nv_bfloat16* __restrict__ attn) {
    extern __shared__ __align__(16) uint32_t sm32[];
    const int tid = threadIdx.x;
    const int b = blockIdx.x >> 6;
    const int h0 = (blockIdx.x & 63) << 1;
    const int hd = blockIdx.y;
    const int grp = hd >> 1;
    const int dil = grp + 1;
    const int cb = grp * 32 + (hd & 1) * 16;
    const int nr = 2 + 2 * dil;

    // zero ONLY the w-pad columns: 512 uint4
    {
        uint4 z = make_uint4(0u, 0u, 0u, 0u);
#pragma unroll
        for (int it = 0; it < 2; it++) {
            int idx = it * 256 + tid;
            int t = idx >> 8, rem = idx & 255;
            int cp = rem >> 5, row = (rem >> 2) & 7, f = rem & 3;
            int off = t * 9216 + cp * 1152 + row * 144
                    + (f < 2 ? f * 4 : 128 + f * 4);
            *(uint4*)(sm32 + off) = z;
        }
    }

    const int baseh = h0 - dil;
    for (int u = tid; u < (nr << 7); u += 256) {
        int q8 = u & 15, seg = u >> 4;
        int cp = seg / nr, row = seg - cp * nr;
        int hr = baseh + row;
        int di = cp * 1152 + row * 144 + 8 + q8 * 8;
        if ((unsigned)hr < 128u) {
            size_t gofs = ((size_t)b << 14) + (hr << 7) + q8 * 8;
            uint4 k0 = *(const uint4*)(qkvp + (((size_t)(96 + cb + 2 * cp)) << 17) + gofs);
            uint4 k1 = *(const uint4*)(qkvp + (((size_t)(97 + cb + 2 * cp)) << 17) + gofs);
            uint4 v0 = *(const uint4*)(qkvp + (((size_t)(192 + cb + 2 * cp)) << 17) + gofs);
            uint4 v1 = *(const uint4*)(qkvp + (((size_t)(193 + cb + 2 * cp)) << 17) + gofs);
            uint4 o;
            o.x = __byte_perm(k0.x, k1.x, 0x5410); o.y = __byte_perm(k0.x, k1.x, 0x7632);
            o.z = __byte_perm(k0.y, k1.y, 0x5410); o.w = __byte_perm(k0.y, k1.y, 0x7632);
            *(uint4*)(sm32 + di) = o;
            o.x = __byte_perm(k0.z, k1.z, 0x5410); o.y = __byte_perm(k0.z, k1.z, 0x7632);
            o.z = __byte_perm(k0.w, k1.w, 0x5410); o.w = __byte_perm(k0.w, k1.w, 0x7632);
            *(uint4*)(sm32 + di + 4) = o;
            o.x = __byte_perm(v0.x, v1.x, 0x5410); o.y = __byte_perm(v0.x, v1.x, 0x7632);
            o.z = __byte_perm(v0.y, v1.y, 0x5410); o.w = __byte_perm(v0.y, v1.y, 0x7632);
            *(uint4*)(sm32 + di + 9216) = o;
            o.x = __byte_perm(v0.z, v1.z, 0x5410); o.y = __byte_perm(v0.z, v1.z, 0x7632);
            o.z = __byte_perm(v0.w, v1.w, 0x5410); o.w = __byte_perm(v0.w, v1.w, 0x7632);
            *(uint4*)(sm32 + di + 9220) = o;
        } else {
            uint4 z = make_uint4(0u, 0u, 0u, 0u);
            *(uint4*)(sm32 + di) = z;        *(uint4*)(sm32 + di + 4) = z;
            *(uint4*)(sm32 + di + 9216) = z; *(uint4*)(sm32 + di + 9220) = z;
        }
    }
    __syncthreads();

    const int r = tid >> 7, w = tid & 127;
    const size_t p = ((size_t)b << 14) + ((size_t)(h0 + r) << 7) + w;

    float ql[8], qh[8];
#pragma unroll
    for (int cp = 0; cp < 8; cp++) {
        ql[cp] = __bfloat162float(qkvp[(((size_t)(cb + 2 * cp)) << 17) + p]);
        qh[cp] = __bfloat162float(qkvp[(((size_t)(cb + 2 * cp + 1)) << 17) + p]);
    }

    float sc[9];
#pragma unroll
    for (int i = 0; i < 3; i++)
#pragma unroll
        for (int j = 0; j < 3; j++) {
            int base = (r + i * dil) * 144 + (8 + w + (j - 1) * dil);
            float d = 0.f;
#pragma unroll
            for (int cp = 0; cp < 8; cp++) {
                uint32_t u = sm32[cp * 1152 + base];
                d = fmaf(ql[cp], bflo(u), d);
                d = fmaf(qh[cp], bfhi(u), d);
            }
            sc[i * 3 + j] = d * 0.25f;
        }

    float mx = sc[0];
#pragma unroll
    for (int k = 1; k < 9; k++) mx = fmaxf(mx, sc[k]);
    float ssum = 0.f;
#pragma unroll
    for (int k = 0; k < 9; k++) { sc[k] = __expf(sc[k] - mx); ssum += sc[k]; }
    float inv = 1.f / ssum;

    float ol[8], oh[8];
#pragma unroll
    for (int cp = 0; cp < 8; cp++) { ol[cp] = 0.f; oh[cp] = 0.f; }
#pragma unroll
    for (int i = 0; i < 3; i++)
#pragma unroll
        for (int j = 0; j < 3; j++) {
            float wgt = sc[i * 3 + j] * inv;
            int base = 9216 + (r + i * dil) * 144 + (8 + w + (j - 1) * dil);
#pragma unroll
            for (int cp = 0; cp < 8; cp++) {
                uint32_t u = sm32[cp * 1152 + base];
                ol[cp] = fmaf(wgt, bflo(u), ol[cp]);
                oh[cp] = fmaf(wgt, bfhi(u), oh[cp]);
            }
        }

    __syncthreads();
#pragma unroll
    for (int cp = 0; cp < 8; cp++)
        sm32[tid * 17 + cp] = packbf(ol[cp], oh[cp]);
    __syncthreads();
    const size_t p0 = ((size_t)b << 14) + ((size_t)h0 << 7);
#pragma unroll
    for (int u = tid; u < 2048; u += 256) {
        int row = u >> 3, wq = u & 7;
        ((uint32_t*)(attn + (p0 + row) * 96 + cb))[wq] = sm32[row * 17 + wq];
    }
}

// ================= mega-fused proj+res+LN2+MLP, x prefetched into SMEM ======
// SMEM map (92672 B -> 2 CTAs/SM):
//   sX  fp32 [96 cols][68] @0   26112  (x residual prefetch, then x1)
//   sA  bf16 [64][104] @26112   13312  (attn A-tile, then LN2 out)
//   sHs bf16 [64][104] @39424   13312  (per-nb h1 block)
//   W0  bf16 [96][104] @52736   19968
//   W1  bf16 [96][104] @72704   19968
//   epilogue staging fp32 [64][97] reuses W0+W1 region @52736.
#define M_SZ 92672

__global__ __launch_bounds__(256, 2)
void k_pm(const __nv_bfloat16* __restrict__ attn,
          const __nv_bfloat16* __restrict__ wp, const float* __restrict__ pb,
          const float* __restrict__ x,
          const __nv_bfloat16* __restrict__ w1, const float* __restrict__ b1,
          const __nv_bfloat16* __restrict__ w2, const float* __restrict__ b2,
          const float* __restrict__ lnw, const float* __restrict__ lnb,
          float* __restrict__ out) {
    extern __shared__ __align__(16) char dsm[];
    const uint32_t sb = smem_u32(dsm);
    float* sX = (float*)dsm;                         // [col*68 + px]
    uint32_t* sAw = (uint32_t*)(dsm + 26112);
    uint32_t* sHsU = (uint32_t*)(dsm + 39424);
    float* sEp = (float*)(dsm + 52736);
    const uint32_t sAa = sb + 26112;
    const uint32_t sHa = sb + 39424;
    const uint32_t W0 = sb + 52736;
    const uint32_t W1 = sb + 72704;

    const int tid = threadIdx.x;
    const int lane = tid & 31;
    const int wid = tid >> 5;
    const int wr = wid >> 2, wc = wid & 3;
    const int g = lane >> 2, tig = lane & 3;
    const int m0 = blockIdx.x * 64;
    const int bb = m0 >> 14, ss0 = m0 & 16383;

    uint32_t aAddr[2], hAddr[2];
#pragma unroll
    for (int i = 0; i < 2; i++) {
        int row = wr * 32 + i * 16 + (lane & 15);
        aAddr[i] = sAa + (uint32_t)(row * 208 + (lane >> 4) * 16);
        hAddr[i] = sHa + (uint32_t)(row * 208 + (lane >> 4) * 16);
    }
    uint32_t bA01, bA2;
    bfrag_addrs<208>(wc, lane, bA01, bA2);

    auto issue_chunk = [&](const __nv_bfloat16* W, int ld, int col0,
                           uint32_t buf) {
        for (int u = tid; u < 1152; u += 256) {
            int rr = u / 12, cc = u - rr * 12;
            cpa16(buf + (uint32_t)(rr * 208 + cc * 16),
                  W + (size_t)rr * ld + col0 + cc * 8);
        }
        cp_commit();
    };

    // ---- L0: x residual (planar -> col-major sX) + attn A-tile + proj W ----
#pragma unroll
    for (int it = 0; it < 6; it++) {                 // 1536 x 16B
        int u = it * 256 + tid;
        int col = u >> 4, q = u & 15;
        cpa16(sb + (uint32_t)(col * 272 + q * 16),
              x + (((size_t)(bb * 96 + col)) << 14) + ss0 + q * 4);
    }
    const __nv_bfloat16* Ab = attn + (size_t)m0 * 96;
#pragma unroll
    for (int it = 0; it < 3; it++) {
        int u = it * 256 + tid;
        int rr = u / 12, cc = u - rr * 12;
        cpa16(sAa + (uint32_t)(rr * 208 + cc * 16), Ab + (size_t)rr * 96 + cc * 8);
    }
    issue_chunk(wp, 96, 0, W0);

#define CHUNK_MMA(ACC, A0, A1, WBUF)                                          \
    do {                                                                      \
        _Pragma("unroll")                                                     \
        for (int ks = 0; ks < 6; ks++) {                                      \
            uint32_t a[2][4], b01[4], b2x[2];                                 \
            LDSM4(b01[0], b01[1], b01[2], b01[3],                             \
                  (WBUF) + bA01 + (uint32_t)(ks * 32));                       \
            LDSM2(b2x[0], b2x[1], (WBUF) + bA2 + (uint32_t)(ks * 32));        \
            LDSM4(a[0][0], a[0][1], a[0][2], a[0][3],                         \
                  (A0) + (uint32_t)(ks * 32));                                \
            LDSM4(a[1][0], a[1][1], a[1][2], a[1][3],                         \
                  (A1) + (uint32_t)(ks * 32));                                \
            _Pragma("unroll")                                                 \
            for (int i = 0; i < 2; i++) {                                     \
                mma16((ACC)[i][0], a[i], b01);                                \
                mma16((ACC)[i][1], a[i], b01 + 2);                            \
                mma16((ACC)[i][2], a[i], b2x);                                \
            }                                                                 \
        }                                                                     \
    } while (0)

    // ---- phase 0: proj (W0); x already resident in sX ----
    float acc[2][3][4];
#pragma unroll
    for (int i = 0; i < 2; i++)
#pragma unroll
        for (int j = 0; j < 3; j++)
#pragma unroll
            for (int q = 0; q < 4; q++) acc[i][j][q] = 0.f;

    cp_wait0(); __syncthreads();
    issue_chunk(w1, 96, 0, W1);                      // fc1 nb0
    CHUNK_MMA(acc, aAddr[0], aAddr[1], W0);

    // ---- x1 = x(sX) + projD + bias, in place ----
#pragma unroll
    for (int i = 0; i < 2; i++)
#pragma unroll
        for (int j = 0; j < 3; j++) {
            int row = wr * 32 + i * 16 + g;
            int col = wc * 24 + j * 8 + 2 * tig;
            float bi0 = __ldg(pb + col), bi1 = __ldg(pb + col + 1);
            sX[col * 68 + row]           += acc[i][j][0] + bi0;
            sX[(col + 1) * 68 + row]     += acc[i][j][1] + bi1;
            sX[col * 68 + row + 8]       += acc[i][j][2] + bi0;
            sX[(col + 1) * 68 + row + 8] += acc[i][j][3] + bi1;
        }
    __syncthreads();

    // ---- LN2: 4 threads per pixel -> sA region ----
    {
        const int px = tid >> 2, q = tid & 3;
        float sum = 0.f, sq = 0.f;
#pragma unroll
        for (int i = 0; i < 24; i++) {
            float v = sX[(q * 24 + i) * 68 + px];
            sum += v;
            sq = fmaf(v, v, sq);
        }
        sum += __shfl_xor_sync(0xffffffffu, sum, 1);
        sq  += __shfl_xor_sync(0xffffffffu, sq, 1);
        sum += __shfl_xor_sync(0xffffffffu, sum, 2);
        sq  += __shfl_xor_sync(0xffffffffu, sq, 2);
        float mu = sum * (1.f / 96.f);
        float rs = rsqrtf(sq * (1.f / 96.f) - mu * mu + 1e-5f);
#pragma unroll
        for (int i = 0; i < 12; i++) {
            int c = q * 24 + 2 * i;
            float a0 = (sX[c * 68 + px] - mu) * rs * __ldg(lnw + c)
                     + __ldg(lnb + c);
            float a1 = (sX[(c + 1) * 68 + px] - mu) * rs * __ldg(lnw + c + 1)
                     + __ldg(lnb + c + 1);
            sAw[px * 52 + q * 12 + i] = packbf(a0, a1);
        }
    }
    // next phase's sync publishes LN2 output

    // ---- interleaved fc1 -> fc2, half-resident A frags for fc1 ----
    float acc2[2][3][4];
#pragma unroll
    for (int i = 0; i < 2; i++)
#pragma unroll
        for (int j = 0; j < 3; j++)
#pragma unroll
            for (int q = 0; q < 4; q++) acc2[i][j][q] = 0.f;

    uint32_t aF[3][2][4];

#pragma unroll 1
    for (int nb = 0; nb < 4; nb++) {
        cp_wait0(); __syncthreads();
        issue_chunk(w2, 384, nb * 96, W0);
        if (nb == 0) {
#pragma unroll
            for (int ks = 0; ks < 3; ks++) {
                LDSM4(aF[ks][0][0], aF[ks][0][1], aF[ks][0][2], aF[ks][0][3],
                      aAddr[0] + (uint32_t)(ks * 32));
                LDSM4(aF[ks][1][0], aF[ks][1][1], aF[ks][1][2], aF[ks][1][3],
                      aAddr[1] + (uint32_t)(ks * 32));
            }
        }
        float a1c[2][3][4];
#pragma unroll
        for (int i = 0; i < 2; i++)
#pragma unroll
            for (int j = 0; j < 3; j++)
#pragma unroll
                for (int q = 0; q < 4; q++) a1c[i][j][q] = 0.f;
#pragma unroll
        for (int ks = 0; ks < 3; ks++) {
            uint32_t b01[4], b2x[2];
            LDSM4(b01[0], b01[1], b01[2], b01[3],
                  W1 + bA01 + (uint32_t)(ks * 32));
            LDSM2(b2x[0], b2x[1], W1 + bA2 + (uint32_t)(ks * 32));
#pragma unroll
            for (int i = 0; i < 2; i++) {
                mma16(a1c[i][0], aF[ks][i], b01);
                mma16(a1c[i][1], aF[ks][i], b01 + 2);
                mma16(a1c[i][2], aF[ks][i], b2x);
            }
        }
#pragma unroll
        for (int ks = 3; ks < 6; ks++) {
            uint32_t a[2][4], b01[4], b2x[2];
            LDSM4(b01[0], b01[1], b01[2], b01[3],
                  W1 + bA01 + (uint32_t)(ks * 32));
            LDSM2(b2x[0], b2x[1], W1 + bA2 + (uint32_t)(ks * 32));
            LDSM4(a[0][0], a[0][1], a[0][2], a[0][3],
                  aAddr[0] + (uint32_t)(ks * 32));
            LDSM4(a[1][0], a[1][1], a[1][2], a[1][3],
                  aAddr[1] + (uint32_t)(ks * 32));
#pragma unroll
            for (int i = 0; i < 2; i++) {
                mma16(a1c[i][0], a[i], b01);
                mma16(a1c[i][1], a[i], b01 + 2);
                mma16(a1c[i][2], a[i], b2x);
            }
        }

#pragma unroll
        for (int i = 0; i < 2; i++)
#pragma unroll
            for (int j = 0; j < 3; j++) {
                int row = wr * 32 + i * 16 + g;
                int col = wc * 24 + j * 8 + 2 * tig;
                float bi0 = __ldg(b1 + nb * 96 + col);
                float bi1 = __ldg(b1 + nb * 96 + col + 1);
                float t0 = gelu_f(a1c[i][j][0] + bi0);
                float t1 = gelu_f(a1c[i][j][1] + bi1);
                float t2 = gelu_f(a1c[i][j][2] + bi0);
                float t3 = gelu_f(a1c[i][j][3] + bi1);
                sHsU[(row * 104 + col) >> 1]       = packbf(t0, t1);
                sHsU[((row + 8) * 104 + col) >> 1] = packbf(t2, t3);
            }

        cp_wait0(); __syncthreads();
        if (nb < 3)
            issue_chunk(w1 + (size_t)(nb + 1) * 9216, 96, 0, W1);
        CHUNK_MMA(acc2, hAddr[0], hAddr[1], W0);
    }
    __syncthreads();

    // ---- epilogue: stage 96 cols fp32, single pass, planar store ----
#pragma unroll
    for (int i = 0; i < 2; i++)
#pragma unroll
        for (int j = 0; j < 3; j++) {
            int row = wr * 32 + i * 16 + g;
            int col = wc * 24 + j * 8 + 2 * tig;
            sEp[row * 97 + col]           = acc2[i][j][0];
            sEp[row * 97 + col + 1]       = acc2[i][j][1];
            sEp[(row + 8) * 97 + col]     = acc2[i][j][2];
            sEp[(row + 8) * 97 + col + 1] = acc2[i][j][3];
        }
    __syncthreads();
#pragma unroll
    for (int u = tid; u < 6144; u += 256) {
        int col = u >> 6, px = u & 63;
        float val = sEp[px * 97 + col] + __ldg(b2 + col) + sX[col * 68 + px];
        out[(((size_t)(bb * 96 + col)) << 14) + ss0 + px] = val;
    }
#undef CHUNK_MMA
}

// ---------------- launch ----------------
extern "C" void kernel_launch(void* const* d_in, const int* in_sizes, int n_in,
                              void* d_out, int out_size) {
    (void)in_sizes; (void)n_in; (void)out_size;
    const float* x      = (const float*)d_in[0];
    const float* qkv_w  = (const float*)d_in[1];
    const float* proj_w = (const float*)d_in[2];
    const float* proj_b = (const float*)d_in[3];
    const float* ln1w   = (const float*)d_in[4];
    const float* ln1b   = (const float*)d_in[5];
    const float* ln2w   = (const float*)d_in[6];
    const float* ln2b   = (const float*)d_in[7];
    const float* fc1w   = (const float*)d_in[8];
    const float* fc1b   = (const float*)d_in[9];
    const float* fc2w   = (const float*)d_in[10];
    const float* fc2b   = (const float*)d_in[11];
    float* out = (float*)d_out;

    cudaFuncSetAttribute(k_ln1_qkv,
                         cudaFuncAttributeMaxDynamicSharedMemorySize, A_SZ);
    cudaFuncSetAttribute(attn_kernel,
                         cudaFuncAttributeMaxDynamicSharedMemorySize, 73728);
    cudaFuncSetAttribute(k_pm,
                         cudaFuncAttributeMaxDynamicSharedMemorySize, M_SZ);

    __nv_bfloat16 *pqkv, *pattn, *pwb;
    cudaGetSymbolAddress((void**)&pqkv, g_qkv);
    cudaGetSymbolAddress((void**)&pattn, g_attn);
    cudaGetSymbolAddress((void**)&pwb, g_wb);

    round_w<<<432, 256>>>(qkv_w, proj_w, fc1w, fc2w);
    k_ln1_qkv<<<PTOT / 128, 256, A_SZ>>>(x, pwb, ln1w, ln1b, pqkv);
    attn_kernel<<<dim3(512, 6), 256, 73728>>>(pqkv, pattn);
    k_pm<<<PTOT / 64, 256, M_SZ>>>(pattn, pwb + 27648, proj_b, x,
                                   pwb + 36864, fc1b, pwb + 73728, fc2b,
                                   ln2w, ln2b, out);
}

// round 15
// speedup vs baseline: 1.0344x; 1.0149x over previous
#include <cuda_runtime.h>
#include <cuda_bf16.h>
#include <cstdint>
#include <cstddef>

// ---------------- problem constants ----------------
#define HW    16384            // 128*128
#define PTOT  131072           // 8*128*128 = 1<<17

// ---------------- scratch (device globals; no allocation) ----------------
// qkv: u32 channel-pair planar [144 pairs][P]; pair pc = channels (2pc, 2pc+1)
__device__ __align__(16) uint32_t      g_qkv [(size_t)PTOT * 144];
__device__ __align__(16) __nv_bfloat16 g_attn[(size_t)PTOT * 96];   // row-major P x 96
__device__ __align__(16) __nv_bfloat16 g_wb  [110592];              // bf16 weights

// ---------------- helpers ----------------
__device__ __forceinline__ uint32_t smem_u32(const void* p) {
    uint32_t a;
    asm("{ .reg .u64 t; cvta.to.shared.u64 t, %1; cvt.u32.u64 %0, t; }"
        : "=r"(a) : "l"(p));
    return a;
}
__device__ __forceinline__ void cpa16(uint32_t dst, const void* src) {
    asm volatile("cp.async.cg.shared.global [%0], [%1], 16;"
                 :: "r"(dst), "l"(src));
}
__device__ __forceinline__ void cp_commit() {
    asm volatile("cp.async.commit_group;" ::: "memory");
}
__device__ __forceinline__ void cp_wait0() {
    asm volatile("cp.async.wait_group 0;" ::: "memory");
}
#define LDSM4(r0, r1, r2, r3, addr) \
    asm volatile("ldmatrix.sync.aligned.m8n8.x4.shared.b16 {%0,%1,%2,%3}, [%4];" \
                 : "=r"(r0), "=r"(r1), "=r"(r2), "=r"(r3) : "r"(addr))
#define LDSM2(r0, r1, addr) \
    asm volatile("ldmatrix.sync.aligned.m8n8.x2.shared.b16 {%0,%1}, [%2];" \
                 : "=r"(r0), "=r"(r1) : "r"(addr))
__device__ __forceinline__ void mma16(float* d, const uint32_t* a,
                                      const uint32_t* b) {
    asm volatile(
        "mma.sync.aligned.m16n8k16.row.col.f32.bf16.bf16.f32 "
        "{%0,%1,%2,%3}, {%4,%5,%6,%7}, {%8,%9}, {%0,%1,%2,%3};"
        : "+f"(d[0]), "+f"(d[1]), "+f"(d[2]), "+f"(d[3])
        : "r"(a[0]), "r"(a[1]), "r"(a[2]), "r"(a[3]), "r"(b[0]), "r"(b[1]));
}
__device__ __forceinline__ uint32_t packbf(float a, float b) {
    __nv_bfloat162 p = __floats2bfloat162_rn(a, b);
    return *(uint32_t*)&p;
}
__device__ __forceinline__ float bflo(uint32_t u) {
    return __uint_as_float(u << 16);
}
__device__ __forceinline__ float bfhi(uint32_t u) {
    return __uint_as_float(u & 0xffff0000u);
}
// tanh-form GELU via hardware MUFU.TANH.
__device__ __forceinline__ float gelu_f(float t) {
    float u = 0.7978845608f * t * fmaf(t * t, 0.044715f, 1.0f);
    float th;
    asm("tanh.approx.f32 %0, %1;" : "=f"(th) : "f"(u));
    return 0.5f * t * (1.f + th);
}

// B-fragment ldmatrix relative addresses, row stride SB bytes.
template <int SB>
__device__ __forceinline__ void bfrag_addrs(int wc, int lane,
                                            uint32_t& bA01, uint32_t& bA2) {
    int rw = lane & 7;
    int hi16 = (lane >> 3) & 1;                // byte +16 = k 8..15
    bA01 = (uint32_t)((wc * 24 + ((lane >> 4) << 3) + rw) * SB + (hi16 << 4));
    bA2  = (uint32_t)((wc * 24 + 16 + rw) * SB + (hi16 << 4));
}

// ---------------- weight conversion fp32 -> bf16 ----------------
__global__ __launch_bounds__(256)
void round_w(const float* __restrict__ qkv, const float* __restrict__ proj,
             const float* __restrict__ fc1, const float* __restrict__ fc2) {
    int i = blockIdx.x * 256 + threadIdx.x;
    float v;
    if (i < 27648)        v = qkv[i];
    else if (i < 36864)   v = proj[i - 27648];
    else if (i < 73728)   v = fc1[i - 36864];
    else                  v = fc2[i - 73728];
    g_wb[i] = __float2bfloat16_rn(v);
}

// ================= fused LN1 + qkv GEMM (256 thr, 2 CTAs/SM) =================
// D staged as u32 channel-pairs [48 pairs][132] and stored planar-packed.
#define A_SZ 91904

__global__ __launch_bounds__(256, 2)
void k_ln1_qkv(const float* __restrict__ x, const __nv_bfloat16* __restrict__ wq,
               const float* __restrict__ lnw, const float* __restrict__ lnb,
               uint32_t* __restrict__ qkv) {
    extern __shared__ __align__(16) char dsm[];
    const uint32_t sb = smem_u32(dsm);
    float* sXp = (float*)dsm;                       // stride 132
    uint32_t* sDp = (uint32_t*)(dsm + 39936);       // [48][132] u32
    uint32_t* sAw = (uint32_t*)(dsm + 65280);
    const uint32_t sAa = sb + 65280;

    const int tid = threadIdx.x;
    const int m0 = blockIdx.x * 128;
    const int bb = m0 >> 14, ss0 = m0 & 16383;

    // ---- stage x (planar) channel-major into sXp ----
#pragma unroll
    for (int it = 0; it < 12; it++) {               // 3072 x 16B
        int u = it * 256 + tid;
        int c = u >> 5, q = u & 31;
        cpa16(sb + (uint32_t)(c * 528 + q * 16),
              x + (((size_t)(bb * 96 + c)) << 14) + ss0 + q * 4);
    }
    cp_commit(); cp_wait0();
    __syncthreads();

    // ---- LN1: two threads per pixel ----
    {
        const int px = tid >> 1, half = tid & 1;
        float sum = 0.f, sq = 0.f;
#pragma unroll
        for (int i = 0; i < 48; i++) {
            float v = sXp[(half * 48 + i) * 132 + px];
            sum += v;
            sq = fmaf(v, v, sq);
        }
        sum += __shfl_xor_sync(0xffffffffu, sum, 1);
        sq  += __shfl_xor_sync(0xffffffffu, sq, 1);
        float mu = sum * (1.f / 96.f);
        float rs = rsqrtf(sq * (1.f / 96.f) - mu * mu + 1e-5f);
#pragma unroll
        for (int i = 0; i < 24; i++) {
            int c = half * 48 + 2 * i;
            float a0 = (sXp[c * 132 + px] - mu) * rs * __ldg(lnw + c)
                     + __ldg(lnb + c);
            float a1 = (sXp[(c + 1) * 132 + px] - mu) * rs * __ldg(lnw + c + 1)
                     + __ldg(lnb + c + 1);
            sAw[px * 52 + half * 24 + i] = packbf(a0, a1);
        }
    }
    __syncthreads();                                // sXp dead; sW region live

    // ---- GEMM over 3 N-blocks, double-buffered weights ----
    const int lane = tid & 31;
    const int wid = tid >> 5;
    const int wr = wid >> 2, wc = wid & 3;
    const int g = lane >> 2, tig = lane & 3;

    uint32_t aAddr[4];
#pragma unroll
    for (int i = 0; i < 4; i++)
        aAddr[i] = sAa + (uint32_t)((wr * 64 + i * 16 + (lane & 15)) * 208
                                    + (lane >> 4) * 16);
    uint32_t bA01, bA2;
    bfrag_addrs<208>(wc, lane, bA01, bA2);

    // preload nb0 weights into buf0
    for (int u = tid; u < 1152; u += 256) {
        int rr = u / 12, cc = u - rr * 12;
        cpa16(sb + (uint32_t)(rr * 208 + cc * 16), wq + rr * 96 + cc * 8);
    }
    cp_commit();

#pragma unroll 1
    for (int nb = 0; nb < 3; nb++) {
        cp_wait0();
        __syncthreads();
        if (nb < 2) {                                // prefetch nb+1
            const __nv_bfloat16* Wn = wq + (size_t)(nb + 1) * 9216;
            uint32_t dst = sb + (uint32_t)(((nb + 1) & 1) * 19968);
            for (int u = tid; u < 1152; u += 256) {
                int rr = u / 12, cc = u - rr * 12;
                cpa16(dst + (uint32_t)(rr * 208 + cc * 16), Wn + rr * 96 + cc * 8);
            }
            cp_commit();
        }
        const uint32_t wb = sb + (uint32_t)((nb & 1) * 19968);

        float acc[4][3][4];
#pragma unroll
        for (int i = 0; i < 4; i++)
#pragma unroll
            for (int j = 0; j < 3; j++)
#pragma unroll
                for (int q = 0; q < 4; q++) acc[i][j][q] = 0.f;

#pragma unroll
        for (int ks = 0; ks < 6; ks++) {
            uint32_t a[4][4], b01[4], b2x[2];
            LDSM4(b01[0], b01[1], b01[2], b01[3], wb + bA01 + (uint32_t)(ks * 32));
            LDSM2(b2x[0], b2x[1], wb + bA2 + (uint32_t)(ks * 32));
#pragma unroll
            for (int i = 0; i < 4; i++)
                LDSM4(a[i][0], a[i][1], a[i][2], a[i][3],
                      aAddr[i] + (uint32_t)(ks * 32));
#pragma unroll
            for (int i = 0; i < 4; i++) {
                mma16(acc[i][0], a[i], b01);
                mma16(acc[i][1], a[i], b01 + 2);
                mma16(acc[i][2], a[i], b2x);
            }
        }

        // stage D as u32 pairs [pc][132]
#pragma unroll
        for (int i = 0; i < 4; i++)
#pragma unroll
            for (int j = 0; j < 3; j++) {
                int row = wr * 64 + i * 16 + g;
                int pc = wc * 12 + j * 4 + tig;      // pair = col/2
                sDp[pc * 132 + row]     = packbf(acc[i][j][0], acc[i][j][1]);
                sDp[pc * 132 + row + 8] = packbf(acc[i][j][2], acc[i][j][3]);
            }
        __syncthreads();
        // store 48 pairs x 128 rows, uint4-vectorized, planar-packed
#pragma unroll
        for (int u = tid; u < 1536; u += 256) {
            int pc = u >> 5, q = u & 31;
            uint4 v = *((const uint4*)(sDp + pc * 132) + q);
            *((uint4*)(qkv + (((size_t)(nb * 48 + pc)) << 17) + m0) + q) = v;
        }
        __syncthreads();
    }
}

// ================= dilated attention (packed pairs; no byte_perm) ==========
// qkv u32 planar [144][P]: q pairs 0-47, k 48-95, v 96-143.
__global__ __launch_bounds__(256)
void attn_kernel(const uint32_t* __restrict__ qkvu,
                 __nv_bfloat16* __restrict__ attn) {
    extern __shared__ __align__(16) uint32_t sm32[];
    const int tid = threadIdx.x;
    const int b = blockIdx.x >> 6;
    const int h0 = (blockIdx.x & 63) << 1;
    const int hd = blockIdx.y;
    const int grp = hd >> 1;
    const int dil = grp + 1;
    const int cb = grp * 32 + (hd & 1) * 16;
    const int cpb = cb >> 1;                         // base pair within 48
    const int nr = 2 + 2 * dil;

    // zero ONLY the w-pad columns: 512 uint4
    {
        uint4 z = make_uint4(0u, 0u, 0u, 0u);
#pragma unroll
        for (int it = 0; it < 2; it++) {
            int idx = it * 256 + tid;
            int t = idx >> 8, rem = idx & 255;
            int cp = rem >> 5, row = (rem >> 2) & 7, f = rem & 3;
            int off = t * 9216 + cp * 1152 + row * 144
                    + (f < 2 ? f * 4 : 128 + f * 4);
            *(uint4*)(sm32 + off) = z;
        }
    }

    const int baseh = h0 - dil;
    for (int u = tid; u < (nr << 7); u += 256) {
        int q8 = u & 15, seg = u >> 4;
        int cp = seg / nr, row = seg - cp * nr;
        int hr = baseh + row;
        int di = cp * 1152 + row * 144 + 8 + q8 * 8;
        if ((unsigned)hr < 128u) {
            size_t gofs = ((size_t)b << 14) + (hr << 7) + q8 * 8;
            const uint32_t* ks = qkvu + (((size_t)(48 + cpb + cp)) << 17) + gofs;
            const uint32_t* vs = qkvu + (((size_t)(96 + cpb + cp)) << 17) + gofs;
            *(uint4*)(sm32 + di)        = *(const uint4*)(ks);
            *(uint4*)(sm32 + di + 4)    = *(const uint4*)(ks + 4);
            *(uint4*)(sm32 + di + 9216) = *(const uint4*)(vs);
            *(uint4*)(sm32 + di + 9220) = *(const uint4*)(vs + 4);
        } else {
            uint4 z = make_uint4(0u, 0u, 0u, 0u);
            *(uint4*)(sm32 + di) = z;        *(uint4*)(sm32 + di + 4) = z;
            *(uint4*)(sm32 + di + 9216) = z; *(uint4*)(sm32 + di + 9220) = z;
        }
    }
    __syncthreads();

    const int r = tid >> 7, w = tid & 127;
    const size_t p = ((size_t)b << 14) + ((size_t)(h0 + r) << 7) + w;

    float ql[8], qh[8];
#pragma unroll
    for (int cp = 0; cp < 8; cp++) {
        uint32_t qv = qkvu[(((size_t)(cpb + cp)) << 17) + p];
        ql[cp] = bflo(qv);
        qh[cp] = bfhi(qv);
    }

    float sc[9];
#pragma unroll
    for (int i = 0; i < 3; i++)
#pragma unroll
        for (int j = 0; j < 3; j++) {
            int base = (r + i * dil) * 144 + (8 + w + (j - 1) * dil);
            float d = 0.f;
#pragma unroll
            for (int cp = 0; cp < 8; cp++) {
                uint32_t u = sm32[cp * 1152 + base];
                d = fmaf(ql[cp], bflo(u), d);
                d = fmaf(qh[cp], bfhi(u), d);
            }
            sc[i * 3 + j] = d * 0.25f;
        }

    float mx = sc[0];
#pragma unroll
    for (int k = 1; k < 9; k++) mx = fmaxf(mx, sc[k]);
    float ssum = 0.f;
#pragma unroll
    for (int k = 0; k < 9; k++) { sc[k] = __expf(sc[k] - mx); ssum += sc[k]; }
    float inv = 1.f / ssum;

    float ol[8], oh[8];
#pragma unroll
    for (int cp = 0; cp < 8; cp++) { ol[cp] = 0.f; oh[cp] = 0.f; }
#pragma unroll
    for (int i = 0; i < 3; i++)
#pragma unroll
        for (int j = 0; j < 3; j++) {
            float wgt = sc[i * 3 + j] * inv;
            int base = 9216 + (r + i * dil) * 144 + (8 + w + (j - 1) * dil);
#pragma unroll
            for (int cp = 0; cp < 8; cp++) {
                uint32_t u = sm32[cp * 1152 + base];
                ol[cp] = fmaf(wgt, bflo(u), ol[cp]);
                oh[cp] = fmaf(wgt, bfhi(u), oh[cp]);
            }
        }

    __syncthreads();
#pragma unroll
    for (int cp = 0; cp < 8; cp++)
        sm32[tid * 17 + cp] = packbf(ol[cp], oh[cp]);
    __syncthreads();
    const size_t p0 = ((size_t)b << 14) + ((size_t)h0 << 7);
#pragma unroll
    for (int u = tid; u < 2048; u += 256) {
        int row = u >> 3, wq = u & 7;
        ((uint32_t*)(attn + (p0 + row) * 96 + cb))[wq] = sm32[row * 17 + wq];
    }
}

// ================= mega-fused proj+res+LN2+MLP (R14 version) ================
#define M_SZ 92672

__global__ __launch_bounds__(256, 2)
void k_pm(const __nv_bfloat16* __restrict__ attn,
          const __nv_bfloat16* __restrict__ wp, const float* __restrict__ pb,
          const float* __restrict__ x,
          const __nv_bfloat16* __restrict__ w1, const float* __restrict__ b1,
          const __nv_bfloat16* __restrict__ w2, const float* __restrict__ b2,
          const float* __restrict__ lnw, const float* __restrict__ lnb,
          float* __restrict__ out) {
    extern __shared__ __align__(16) char dsm[];
    const uint32_t sb = smem_u32(dsm);
    float* sX = (float*)dsm;                         // [col*68 + px]
    uint32_t* sAw = (uint32_t*)(dsm + 26112);
    uint32_t* sHsU = (uint32_t*)(dsm + 39424);
    float* sEp = (float*)(dsm + 52736);
    const uint32_t sAa = sb + 26112;
    const uint32_t sHa = sb + 39424;
    const uint32_t W0 = sb + 52736;
    const uint32_t W1 = sb + 72704;

    const int tid = threadIdx.x;
    const int lane = tid & 31;
    const int wid = tid >> 5;
    const int wr = wid >> 2, wc = wid & 3;
    const int g = lane >> 2, tig = lane & 3;
    const int m0 = blockIdx.x * 64;
    const int bb = m0 >> 14, ss0 = m0 & 16383;

    uint32_t aAddr[2], hAddr[2];
#pragma unroll
    for (int i = 0; i < 2; i++) {
        int row = wr * 32 + i * 16 + (lane & 15);
        aAddr[i] = sAa + (uint32_t)(row * 208 + (lane >> 4) * 16);
        hAddr[i] = sHa + (uint32_t)(row * 208 + (lane >> 4) * 16);
    }
    uint32_t bA01, bA2;
    bfrag_addrs<208>(wc, lane, bA01, bA2);

    auto issue_chunk = [&](const __nv_bfloat16* W, int ld, int col0,
                           uint32_t buf) {
        for (int u = tid; u < 1152; u += 256) {
            int rr = u / 12, cc = u - rr * 12;
            cpa16(buf + (uint32_t)(rr * 208 + cc * 16),
                  W + (size_t)rr * ld + col0 + cc * 8);
        }
        cp_commit();
    };

    // ---- L0: x residual (planar -> col-major sX) + attn A-tile + proj W ----
#pragma unroll
    for (int it = 0; it < 6; it++) {                 // 1536 x 16B
        int u = it * 256 + tid;
        int col = u >> 4, q = u & 15;
        cpa16(sb + (uint32_t)(col * 272 + q * 16),
              x + (((size_t)(bb * 96 + col)) << 14) + ss0 + q * 4);
    }
    const __nv_bfloat16* Ab = attn + (size_t)m0 * 96;
#pragma unroll
    for (int it = 0; it < 3; it++) {
        int u = it * 256 + tid;
        int rr = u / 12, cc = u - rr * 12;
        cpa16(sAa + (uint32_t)(rr * 208 + cc * 16), Ab + (size_t)rr * 96 + cc * 8);
    }
    issue_chunk(wp, 96, 0, W0);

#define CHUNK_MMA(ACC, A0, A1, WBUF)                                          \
    do {                                                                      \
        _Pragma("unroll")                                                     \
        for (int ks = 0; ks < 6; ks++) {                                      \
            uint32_t a[2][4], b01[4], b2x[2];                                 \
            LDSM4(b01[0], b01[1], b01[2], b01[3],                             \
                  (WBUF) + bA01 + (uint32_t)(ks * 32));                       \
            LDSM2(b2x[0], b2x[1], (WBUF) + bA2 + (uint32_t)(ks * 32));        \
            LDSM4(a[0][0], a[0][1], a[0][2], a[0][3],                         \
                  (A0) + (uint32_t)(ks * 32));                                \
            LDSM4(a[1][0], a[1][1], a[1][2], a[1][3],                         \
                  (A1) + (uint32_t)(ks * 32));                                \
            _Pragma("unroll")                                                 \
            for (int i = 0; i < 2; i++) {                                     \
                mma16((ACC)[i][0], a[i], b01);                                \
                mma16((ACC)[i][1], a[i], b01 + 2);                            \
                mma16((ACC)[i][2], a[i], b2x);                                \
            }                                                                 \
        }                                                                     \
    } while (0)

    // ---- phase 0: proj (W0); x already resident in sX ----
    float acc[2][3][4];
#pragma unroll
    for (int i = 0; i < 2; i++)
#pragma unroll
        for (int j = 0; j < 3; j++)
#pragma unroll
            for (int q = 0; q < 4; q++) acc[i][j][q] = 0.f;

    cp_wait0(); __syncthreads();
    issue_chunk(w1, 96, 0, W1);                      // fc1 nb0
    CHUNK_MMA(acc, aAddr[0], aAddr[1], W0);

    // ---- x1 = x(sX) + projD + bias, in place ----
#pragma unroll
    for (int i = 0; i < 2; i++)
#pragma unroll
        for (int j = 0; j < 3; j++) {
            int row = wr * 32 + i * 16 + g;
            int col = wc * 24 + j * 8 + 2 * tig;
            float bi0 = __ldg(pb + col), bi1 = __ldg(pb + col + 1);
            sX[col * 68 + row]           += acc[i][j][0] + bi0;
            sX[(col + 1) * 68 + row]     += acc[i][j][1] + bi1;
            sX[col * 68 + row + 8]       += acc[i][j][2] + bi0;
            sX[(col + 1) * 68 + row + 8] += acc[i][j][3] + bi1;
        }
    __syncthreads();

    // ---- LN2: 4 threads per pixel -> sA region ----
    {
        const int px = tid >> 2, q = tid & 3;
        float sum = 0.f, sq = 0.f;
#pragma unroll
        for (int i = 0; i < 24; i++) {
            float v = sX[(q * 24 + i) * 68 + px];
            sum += v;
            sq = fmaf(v, v, sq);
        }
        sum += __shfl_xor_sync(0xffffffffu, sum, 1);
        sq  += __shfl_xor_sync(0xffffffffu, sq, 1);
        sum += __shfl_xor_sync(0xffffffffu, sum, 2);
        sq  += __shfl_xor_sync(0xffffffffu, sq, 2);
        float mu = sum * (1.f / 96.f);
        float rs = rsqrtf(sq * (1.f / 96.f) - mu * mu + 1e-5f);
#pragma unroll
        for (int i = 0; i < 12; i++) {
            int c = q * 24 + 2 * i;
            float a0 = (sX[c * 68 + px] - mu) * rs * __ldg(lnw + c)
                     + __ldg(lnb + c);
            float a1 = (sX[(c + 1) * 68 + px] - mu) * rs * __ldg(lnw + c + 1)
                     + __ldg(lnb + c + 1);
            sAw[px * 52 + q * 12 + i] = packbf(a0, a1);
        }
    }
    // next phase's sync publishes LN2 output

    // ---- interleaved fc1 -> fc2, half-resident A frags for fc1 ----
    float acc2[2][3][4];
#pragma unroll
    for (int i = 0; i < 2; i++)
#pragma unroll
        for (int j = 0; j < 3; j++)
#pragma unroll
            for (int q = 0; q < 4; q++) acc2[i][j][q] = 0.f;

    uint32_t aF[3][2][4];

#pragma unroll 1
    for (int nb = 0; nb < 4; nb++) {
        cp_wait0(); __syncthreads();
        issue_chunk(w2, 384, nb * 96, W0);
        if (nb == 0) {
#pragma unroll
            for (int ks = 0; ks < 3; ks++) {
                LDSM4(aF[ks][0][0], aF[ks][0][1], aF[ks][0][2], aF[ks][0][3],
                      aAddr[0] + (uint32_t)(ks * 32));
                LDSM4(aF[ks][1][0], aF[ks][1][1], aF[ks][1][2], aF[ks][1][3],
                      aAddr[1] + (uint32_t)(ks * 32));
            }
        }
        float a1c[2][3][4];
#pragma unroll
        for (int i = 0; i < 2; i++)
#pragma unroll
            for (int j = 0; j < 3; j++)
#pragma unroll
                for (int q = 0; q < 4; q++) a1c[i][j][q] = 0.f;
#pragma unroll
        for (int ks = 0; ks < 3; ks++) {
            uint32_t b01[4], b2x[2];
            LDSM4(b01[0], b01[1], b01[2], b01[3],
                  W1 + bA01 + (uint32_t)(ks * 32));
            LDSM2(b2x[0], b2x[1], W1 + bA2 + (uint32_t)(ks * 32));
#pragma unroll
            for (int i = 0; i < 2; i++) {
                mma16(a1c[i][0], aF[ks][i], b01);
                mma16(a1c[i][1], aF[ks][i], b01 + 2);
                mma16(a1c[i][2], aF[ks][i], b2x);
            }
        }
#pragma unroll
        for (int ks = 3; ks < 6; ks++) {
            uint32_t a[2][4], b01[4], b2x[2];
            LDSM4(b01[0], b01[1], b01[2], b01[3],
                  W1 + bA01 + (uint32_t)(ks * 32));
            LDSM2(b2x[0], b2x[1], W1 + bA2 + (uint32_t)(ks * 32));
            LDSM4(a[0][0], a[0][1], a[0][2], a[0][3],
                  aAddr[0] + (uint32_t)(ks * 32));
            LDSM4(a[1][0], a[1][1], a[1][2], a[1][3],
                  aAddr[1] + (uint32_t)(ks * 32));
#pragma unroll
            for (int i = 0; i < 2; i++) {
                mma16(a1c[i][0], a[i], b01);
                mma16(a1c[i][1], a[i], b01 + 2);
                mma16(a1c[i][2], a[i], b2x);
            }
        }

#pragma unroll
        for (int i = 0; i < 2; i++)
#pragma unroll
            for (int j = 0; j < 3; j++) {
                int row = wr * 32 + i * 16 + g;
                int col = wc * 24 + j * 8 + 2 * tig;
                float bi0 = __ldg(b1 + nb * 96 + col);
                float bi1 = __ldg(b1 + nb * 96 + col + 1);
                float t0 = gelu_f(a1c[i][j][0] + bi0);
                float t1 = gelu_f(a1c[i][j][1] + bi1);
                float t2 = gelu_f(a1c[i][j][2] + bi0);
                float t3 = gelu_f(a1c[i][j][3] + bi1);
                sHsU[(row * 104 + col) >> 1]       = packbf(t0, t1);
                sHsU[((row + 8) * 104 + col) >> 1] = packbf(t2, t3);
            }

        cp_wait0(); __syncthreads();
        if (nb < 3)
            issue_chunk(w1 + (size_t)(nb + 1) * 9216, 96, 0, W1);
        CHUNK_MMA(acc2, hAddr[0], hAddr[1], W0);
    }
    __syncthreads();

    // ---- epilogue: stage 96 cols fp32, single pass, planar store ----
#pragma unroll
    for (int i = 0; i < 2; i++)
#pragma unroll
        for (int j = 0; j < 3; j++) {
            int row = wr * 32 + i * 16 + g;
            int col = wc * 24 + j * 8 + 2 * tig;
            sEp[row * 97 + col]           = acc2[i][j][0];
            sEp[row * 97 + col + 1]       = acc2[i][j][1];
            sEp[(row + 8) * 97 + col]     = acc2[i][j][2];
            sEp[(row + 8) * 97 + col + 1] = acc2[i][j][3];
        }
    __syncthreads();
#pragma unroll
    for (int u = tid; u < 6144; u += 256) {
        int col = u >> 6, px = u & 63;
        float val = sEp[px * 97 + col] + __ldg(b2 + col) + sX[col * 68 + px];
        out[(((size_t)(bb * 96 + col)) << 14) + ss0 + px] = val;
    }
#undef CHUNK_MMA
}

// ---------------- launch ----------------
extern "C" void kernel_launch(void* const* d_in, const int* in_sizes, int n_in,
                              void* d_out, int out_size) {
    (void)in_sizes; (void)n_in; (void)out_size;
    const float* x      = (const float*)d_in[0];
    const float* qkv_w  = (const float*)d_in[1];
    const float* proj_w = (const float*)d_in[2];
    const float* proj_b = (const float*)d_in[3];
    const float* ln1w   = (const float*)d_in[4];
    const float* ln1b   = (const float*)d_in[5];
    const float* ln2w   = (const float*)d_in[6];
    const float* ln2b   = (const float*)d_in[7];
    const float* fc1w   = (const float*)d_in[8];
    const float* fc1b   = (const float*)d_in[9];
    const float* fc2w   = (const float*)d_in[10];
    const float* fc2b   = (const float*)d_in[11];
    float* out = (float*)d_out;

    cudaFuncSetAttribute(k_ln1_qkv,
                         cudaFuncAttributeMaxDynamicSharedMemorySize, A_SZ);
    cudaFuncSetAttribute(attn_kernel,
                         cudaFuncAttributeMaxDynamicSharedMemorySize, 73728);
    cudaFuncSetAttribute(k_pm,
                         cudaFuncAttributeMaxDynamicSharedMemorySize, M_SZ);

    uint32_t* pqkv;
    __nv_bfloat16 *pattn, *pwb;
    cudaGetSymbolAddress((void**)&pqkv, g_qkv);
    cudaGetSymbolAddress((void**)&pattn, g_attn);
    cudaGetSymbolAddress((void**)&pwb, g_wb);

    round_w<<<432, 256>>>(qkv_w, proj_w, fc1w, fc2w);
    k_ln1_qkv<<<PTOT / 128, 256, A_SZ>>>(x, pwb, ln1w, ln1b, pqkv);
    attn_kernel<<<dim3(512, 6), 256, 73728>>>(pqkv, pattn);
    k_pm<<<PTOT / 64, 256, M_SZ>>>(pattn, pwb + 27648, proj_b, x,
                                   pwb + 36864, fc1b, pwb + 73728, fc2b,
                                   ln2w, ln2b, out);
}